// round 2
// baseline (speedup 1.0000x reference)
#include <cuda_runtime.h>
#include <math.h>

#define B_ 8
#define L_ 2048
#define E_ 512
#define D_ 64
#define HH 64
#define WW 64
#define HW 4096
#define STEPS_ 5

// ---------------- scratch (device globals; no allocation) ----------------
__device__ float g_gyi[B_*L_*HH];   // gy_in scaled by 1/norm_in
__device__ float g_gxi[B_*L_*WW];   // gx_in raw
__device__ float g_gyo[B_*L_*HH];   // gy_out scaled by 1/norm_out
__device__ float g_gxo[B_*L_*WW];   // gx_out raw
__device__ float g_proj[B_*L_*D_];      // (b,l,d)
__device__ float g_field[B_*D_*HW];     // (b,c,h,w)
__device__ float g_hbuf[B_*2*D_*HW];    // (b,2D,h,w)
__device__ float g_sampled[B_*L_*D_];   // (b,l,c)

// ---------------- K0: separable gaussians + normalizers ----------------
__global__ void k_gauss(const float* __restrict__ pos,
                        const float* __restrict__ log_sigma) {
    int bl = blockIdx.x;
    int t  = threadIdx.x;   // 0..63, serves as h and w index
    float ls = *log_sigma;
    float si = log1pf(expf(ls)) + 1e-6f;
    float so = 2.0f * si;
    float i2si = 1.0f / (2.0f * si * si);
    float i2so = 1.0f / (2.0f * so * so);
    float py = pos[bl*2+0];
    float px = pos[bl*2+1];
    float d  = (float)t;
    float dy2 = (d - py) * (d - py);
    float dx2 = (d - px) * (d - px);
    float gy  = expf(-dy2 * i2si);
    float gx  = expf(-dx2 * i2si);
    float gyo = expf(-dy2 * i2so);
    float gxo = expf(-dx2 * i2so);
    __shared__ float red[4][64];
    __shared__ float sums[4];
    red[0][t]=gy; red[1][t]=gx; red[2][t]=gyo; red[3][t]=gxo;
    __syncthreads();
    if (t < 4) {
        float s = 0.0f;
        #pragma unroll
        for (int i = 0; i < 64; i++) s += red[t][i];
        sums[t] = s;
    }
    __syncthreads();
    float inv_ni = 1.0f / (sums[0]*sums[1] + 1e-6f);
    float inv_no = 1.0f / (sums[2]*sums[3] + 1e-6f);
    int base = bl*64 + t;
    g_gyi[base] = gy  * inv_ni;
    g_gxi[base] = gx;
    g_gyo[base] = gyo * inv_no;
    g_gxo[base] = gxo;
}

// ---------------- K1: proj = tokens @ W_to_field^T  (16384x64, K=512) ----
__global__ void __launch_bounds__(256)
k_proj(const float* __restrict__ tokens, const float* __restrict__ Wt) {
    __shared__ float As[32][132];   // [e][m]  (m = token row)
    __shared__ float Bs[32][68];    // [e][d]
    int m0 = blockIdx.x * 128;
    int tx = threadIdx.x;
    int m_base = (tx >> 4) * 8;
    int n_base = (tx & 15) * 4;
    float acc[8][4] = {};
    for (int k0 = 0; k0 < 512; k0 += 32) {
        for (int i = tx; i < 32*128; i += 256) {
            int e = i & 31, m = i >> 5;
            As[e][m] = tokens[(m0+m)*512 + k0 + e];
        }
        for (int i = tx; i < 32*64; i += 256) {
            int e = i & 31, dch = i >> 5;
            Bs[e][dch] = Wt[dch*512 + k0 + e];
        }
        __syncthreads();
        #pragma unroll 4
        for (int kk = 0; kk < 32; kk++) {
            float4 a0 = *(const float4*)&As[kk][m_base];
            float4 a1 = *(const float4*)&As[kk][m_base+4];
            float4 bv = *(const float4*)&Bs[kk][n_base];
            float am[8] = {a0.x,a0.y,a0.z,a0.w,a1.x,a1.y,a1.z,a1.w};
            float bn[4] = {bv.x,bv.y,bv.z,bv.w};
            #pragma unroll
            for (int i2 = 0; i2 < 8; i2++)
                #pragma unroll
                for (int j = 0; j < 4; j++)
                    acc[i2][j] = fmaf(am[i2], bn[j], acc[i2][j]);
        }
        __syncthreads();
    }
    #pragma unroll
    for (int i2 = 0; i2 < 8; i2++) {
        float4 v = make_float4(acc[i2][0],acc[i2][1],acc[i2][2],acc[i2][3]);
        *(float4*)&g_proj[(m0+m_base+i2)*64 + n_base] = v;
    }
}

// ------- K2: scatter. field[b](64 x 4096) = proj^T * (gy ⊗ gx) ---------
__global__ void __launch_bounds__(256) k_scatter() {
    __shared__ float As[32][68];    // [k=l][c]
    __shared__ float Bs[32][132];   // [k][n=hw]
    int b  = blockIdx.y;
    int n0 = blockIdx.x * 128;      // hw tile (2 rows of 64)
    int h0 = n0 >> 6;
    int tx = threadIdx.x;
    int m_base = (tx >> 5) * 8;
    int n_base = (tx & 31) * 4;
    float acc[8][4] = {};
    for (int l0 = 0; l0 < L_; l0 += 32) {
        for (int i = tx; i < 32*64; i += 256) {
            int c = i & 63, k = i >> 6;
            As[k][c] = g_proj[((size_t)(b*L_) + l0 + k)*64 + c];
        }
        for (int i = tx; i < 32*128; i += 256) {
            int n = i & 127, k = i >> 7;
            int l = l0 + k;
            float gy = g_gyi[(b*L_+l)*64 + h0 + (n >> 6)];
            float gx = g_gxi[(b*L_+l)*64 + (n & 63)];
            Bs[k][n] = gy * gx;
        }
        __syncthreads();
        #pragma unroll 4
        for (int kk = 0; kk < 32; kk++) {
            float4 a0 = *(const float4*)&As[kk][m_base];
            float4 a1 = *(const float4*)&As[kk][m_base+4];
            float4 bv = *(const float4*)&Bs[kk][n_base];
            float am[8] = {a0.x,a0.y,a0.z,a0.w,a1.x,a1.y,a1.z,a1.w};
            float bn[4] = {bv.x,bv.y,bv.z,bv.w};
            #pragma unroll
            for (int i2 = 0; i2 < 8; i2++)
                #pragma unroll
                for (int j = 0; j < 4; j++)
                    acc[i2][j] = fmaf(am[i2], bn[j], acc[i2][j]);
        }
        __syncthreads();
    }
    #pragma unroll
    for (int i2 = 0; i2 < 8; i2++) {
        float4 v = make_float4(acc[i2][0],acc[i2][1],acc[i2][2],acc[i2][3]);
        *(float4*)&g_field[((size_t)(b*64) + m_base + i2)*HW + n0 + n_base] = v;
    }
}

// ---- K3: conv1 3x3 (64->128) + bias + relu, implicit GEMM ----
__global__ void __launch_bounds__(256)
k_conv1(const float* __restrict__ w1, const float* __restrict__ b1) {
    __shared__ float As[36][68];    // [k=(ici*9+tap)][oc_local]
    __shared__ float Bs[36][132];   // [k][n=pixel]
    int b   = blockIdx.z;
    int oc0 = blockIdx.y * 64;
    int y0  = blockIdx.x * 2;       // two output rows
    int p0  = y0 * 64;
    int tx  = threadIdx.x;
    int m_base = (tx >> 5) * 8;
    int n_base = (tx & 31) * 4;
    float acc[8][4] = {};
    for (int ic0 = 0; ic0 < 64; ic0 += 4) {
        for (int i = tx; i < 36*64; i += 256) {
            int k = i % 36, ocl = i / 36;
            As[k][ocl] = w1[(oc0+ocl)*576 + ic0*9 + k];
        }
        for (int i = tx; i < 36*128; i += 256) {
            int n = i & 127, k = i >> 7;
            int ici = k / 9, tap = k - ici*9;
            int ky = tap / 3, kx = tap - ky*3;
            int y = y0 + (n >> 6) + ky - 1;
            int x = (n & 63) + kx - 1;
            float v = 0.0f;
            if ((unsigned)y < 64u && (unsigned)x < 64u)
                v = g_field[((size_t)(b*64) + ic0 + ici)*HW + y*64 + x];
            Bs[k][n] = v;
        }
        __syncthreads();
        #pragma unroll 4
        for (int kk = 0; kk < 36; kk++) {
            float4 a0 = *(const float4*)&As[kk][m_base];
            float4 a1 = *(const float4*)&As[kk][m_base+4];
            float4 bv = *(const float4*)&Bs[kk][n_base];
            float am[8] = {a0.x,a0.y,a0.z,a0.w,a1.x,a1.y,a1.z,a1.w};
            float bn[4] = {bv.x,bv.y,bv.z,bv.w};
            #pragma unroll
            for (int i2 = 0; i2 < 8; i2++)
                #pragma unroll
                for (int j = 0; j < 4; j++)
                    acc[i2][j] = fmaf(am[i2], bn[j], acc[i2][j]);
        }
        __syncthreads();
    }
    #pragma unroll
    for (int i2 = 0; i2 < 8; i2++) {
        int oc = oc0 + m_base + i2;
        float bias = b1[oc];
        float4 v = make_float4(fmaxf(acc[i2][0]+bias, 0.0f),
                               fmaxf(acc[i2][1]+bias, 0.0f),
                               fmaxf(acc[i2][2]+bias, 0.0f),
                               fmaxf(acc[i2][3]+bias, 0.0f));
        *(float4*)&g_hbuf[((size_t)(b*128) + oc)*HW + p0 + n_base] = v;
    }
}

// ---- K4: conv2 1x1 (128->64) + bias + residual, in-place on field ----
__global__ void __launch_bounds__(256)
k_conv2(const float* __restrict__ w2, const float* __restrict__ b2) {
    __shared__ float As[32][68];    // [k][c]
    __shared__ float Bs[32][132];   // [k][n]
    int b  = blockIdx.y;
    int p0 = blockIdx.x * 128;
    int tx = threadIdx.x;
    int m_base = (tx >> 5) * 8;
    int n_base = (tx & 31) * 4;
    float acc[8][4] = {};
    for (int k0 = 0; k0 < 128; k0 += 32) {
        for (int i = tx; i < 32*64; i += 256) {
            int k = i & 31, c = i >> 5;
            As[k][c] = w2[c*128 + k0 + k];
        }
        for (int i = tx; i < 32*128; i += 256) {
            int n = i & 127, k = i >> 7;
            Bs[k][n] = g_hbuf[((size_t)(b*128) + k0 + k)*HW + p0 + n];
        }
        __syncthreads();
        #pragma unroll 4
        for (int kk = 0; kk < 32; kk++) {
            float4 a0 = *(const float4*)&As[kk][m_base];
            float4 a1 = *(const float4*)&As[kk][m_base+4];
            float4 bv = *(const float4*)&Bs[kk][n_base];
            float am[8] = {a0.x,a0.y,a0.z,a0.w,a1.x,a1.y,a1.z,a1.w};
            float bn[4] = {bv.x,bv.y,bv.z,bv.w};
            #pragma unroll
            for (int i2 = 0; i2 < 8; i2++)
                #pragma unroll
                for (int j = 0; j < 4; j++)
                    acc[i2][j] = fmaf(am[i2], bn[j], acc[i2][j]);
        }
        __syncthreads();
    }
    #pragma unroll
    for (int i2 = 0; i2 < 8; i2++) {
        int c = m_base + i2;
        float bias = b2[c];
        size_t off = ((size_t)(b*64) + c)*HW + p0 + n_base;
        float4 r = *(const float4*)&g_field[off];
        float4 v = make_float4(acc[i2][0]+bias+r.x, acc[i2][1]+bias+r.y,
                               acc[i2][2]+bias+r.z, acc[i2][3]+bias+r.w);
        *(float4*)&g_field[off] = v;
    }
}

// ---- K5: gather. sampled[b](L x 64) = (gyo ⊗ gxo) * field^T ----
__global__ void __launch_bounds__(256) k_gather() {
    __shared__ float As[64][68];    // [k=w][l]
    __shared__ float Bs[64][68];    // [k=w][c]
    int b  = blockIdx.y;
    int l0 = blockIdx.x * 64;
    int tx = threadIdx.x;
    int m_base = (tx >> 4) * 4;     // l
    int n_base = (tx & 15) * 4;     // c
    float acc[4][4] = {};
    for (int h = 0; h < 64; h++) {
        for (int i = tx; i < 64*64; i += 256) {
            int w = i & 63, l = i >> 6;
            float gy = g_gyo[(b*L_ + l0 + l)*64 + h];
            float gx = g_gxo[(b*L_ + l0 + l)*64 + w];
            As[w][l] = gy * gx;
        }
        for (int i = tx; i < 64*64; i += 256) {
            int w = i & 63, c = i >> 6;
            Bs[w][c] = g_field[((size_t)(b*64) + c)*HW + h*64 + w];
        }
        __syncthreads();
        #pragma unroll 4
        for (int kk = 0; kk < 64; kk++) {
            float4 a = *(const float4*)&As[kk][m_base];
            float4 bv = *(const float4*)&Bs[kk][n_base];
            float am[4] = {a.x,a.y,a.z,a.w};
            float bn[4] = {bv.x,bv.y,bv.z,bv.w};
            #pragma unroll
            for (int i2 = 0; i2 < 4; i2++)
                #pragma unroll
                for (int j = 0; j < 4; j++)
                    acc[i2][j] = fmaf(am[i2], bn[j], acc[i2][j]);
        }
        __syncthreads();
    }
    #pragma unroll
    for (int i2 = 0; i2 < 4; i2++) {
        float4 v = make_float4(acc[i2][0],acc[i2][1],acc[i2][2],acc[i2][3]);
        *(float4*)&g_sampled[((size_t)(b*L_) + l0 + m_base + i2)*64 + n_base] = v;
    }
}

// ---- K6: tokens_out = sampled @ W_from_field^T  (16384x512, K=64) ----
__global__ void __launch_bounds__(256)
k_out(const float* __restrict__ Wf, float* __restrict__ out) {
    __shared__ float As[64][68];    // [c][m=l]
    __shared__ float Bs[64][68];    // [c][e]
    int m0 = blockIdx.x * 64;
    int e0 = blockIdx.y * 64;
    int tx = threadIdx.x;
    int m_base = (tx >> 4) * 4;
    int n_base = (tx & 15) * 4;
    float acc[4][4] = {};
    for (int i = tx; i < 64*64; i += 256) {
        int c = i & 63, m = i >> 6;
        As[c][m] = g_sampled[(size_t)(m0+m)*64 + c];
    }
    for (int i = tx; i < 64*64; i += 256) {
        int c = i & 63, e = i >> 6;
        Bs[c][e] = Wf[(e0+e)*64 + c];
    }
    __syncthreads();
    #pragma unroll 4
    for (int kk = 0; kk < 64; kk++) {
        float4 a = *(const float4*)&As[kk][m_base];
        float4 bv = *(const float4*)&Bs[kk][n_base];
        float am[4] = {a.x,a.y,a.z,a.w};
        float bn[4] = {bv.x,bv.y,bv.z,bv.w};
        #pragma unroll
        for (int i2 = 0; i2 < 4; i2++)
            #pragma unroll
            for (int j = 0; j < 4; j++)
                acc[i2][j] = fmaf(am[i2], bn[j], acc[i2][j]);
    }
    #pragma unroll
    for (int i2 = 0; i2 < 4; i2++) {
        float4 v = make_float4(acc[i2][0],acc[i2][1],acc[i2][2],acc[i2][3]);
        *(float4*)&out[(size_t)(m0+m_base+i2)*512 + e0 + n_base] = v;
    }
}

// ------------------------------ launch -----------------------------------
extern "C" void kernel_launch(void* const* d_in, const int* in_sizes, int n_in,
                              void* d_out, int out_size) {
    const float* tokens     = (const float*)d_in[0];
    const float* positions  = (const float*)d_in[1];
    const float* W_to_field = (const float*)d_in[2];
    const float* W_from_field = (const float*)d_in[3];
    const float* conv1_w    = (const float*)d_in[4];
    const float* conv1_b    = (const float*)d_in[5];
    const float* conv2_w    = (const float*)d_in[6];
    const float* conv2_b    = (const float*)d_in[7];
    const float* log_sigma  = (const float*)d_in[8];
    float* out = (float*)d_out;

    k_gauss<<<B_*L_, 64>>>(positions, log_sigma);
    k_proj<<<(B_*L_)/128, 256>>>(tokens, W_to_field);
    k_scatter<<<dim3(32, B_), 256>>>();
    for (int s = 0; s < STEPS_; s++) {
        k_conv1<<<dim3(32, 2, B_), 256>>>(conv1_w, conv1_b);
        k_conv2<<<dim3(32, B_), 256>>>(conv2_w, conv2_b);
    }
    k_gather<<<dim3(32, B_), 256>>>();
    k_out<<<dim3((B_*L_)/64, 8), 256>>>(W_from_field, out);
}

// round 3
// speedup vs baseline: 1.1232x; 1.1232x over previous
#include <cuda_runtime.h>
#include <math.h>

#define B_ 8
#define L_ 2048
#define E_ 512
#define D_ 64
#define HH 64
#define WW 64
#define HW 4096
#define STEPS_ 5

// ---------------- scratch (device globals; no allocation) ----------------
__device__ float g_gyi[B_*L_*HH];   // gy_in scaled by 1/norm_in
__device__ float g_gxi[B_*L_*WW];   // gx_in raw
__device__ float g_gyo[B_*L_*HH];   // gy_out scaled by 1/norm_out
__device__ float g_gxo[B_*L_*WW];   // gx_out raw
__device__ float g_proj[B_*L_*D_];      // (b,l,d)
__device__ float g_field[B_*D_*HW];     // buffer A
__device__ float g_field2[B_*D_*HW];    // buffer B
__device__ float g_sampled[B_*L_*D_];   // (b,l,c)

// ---------------- K0: separable gaussians + normalizers ----------------
__global__ void k_gauss(const float* __restrict__ pos,
                        const float* __restrict__ log_sigma) {
    int bl = blockIdx.x;
    int t  = threadIdx.x;   // 0..63, serves as h and w index
    float ls = *log_sigma;
    float si = log1pf(expf(ls)) + 1e-6f;
    float so = 2.0f * si;
    float i2si = 1.0f / (2.0f * si * si);
    float i2so = 1.0f / (2.0f * so * so);
    float py = pos[bl*2+0];
    float px = pos[bl*2+1];
    float d  = (float)t;
    float dy2 = (d - py) * (d - py);
    float dx2 = (d - px) * (d - px);
    float gy  = expf(-dy2 * i2si);
    float gx  = expf(-dx2 * i2si);
    float gyo = expf(-dy2 * i2so);
    float gxo = expf(-dx2 * i2so);
    __shared__ float red[4][64];
    __shared__ float sums[4];
    red[0][t]=gy; red[1][t]=gx; red[2][t]=gyo; red[3][t]=gxo;
    __syncthreads();
    if (t < 4) {
        float s = 0.0f;
        #pragma unroll
        for (int i = 0; i < 64; i++) s += red[t][i];
        sums[t] = s;
    }
    __syncthreads();
    float inv_ni = 1.0f / (sums[0]*sums[1] + 1e-6f);
    float inv_no = 1.0f / (sums[2]*sums[3] + 1e-6f);
    int base = bl*64 + t;
    g_gyi[base] = gy  * inv_ni;
    g_gxi[base] = gx;
    g_gyo[base] = gyo * inv_no;
    g_gxo[base] = gxo;
}

// ---------------- K1: proj = tokens @ W_to_field^T  (16384x64, K=512) ----
__global__ void __launch_bounds__(256)
k_proj(const float* __restrict__ tokens, const float* __restrict__ Wt) {
    __shared__ float As[32][132];   // [e][m]  (m = token row)
    __shared__ float Bs[32][68];    // [e][d]
    int m0 = blockIdx.x * 128;
    int tx = threadIdx.x;
    int m_base = (tx >> 4) * 8;
    int n_base = (tx & 15) * 4;
    float acc[8][4] = {};
    for (int k0 = 0; k0 < 512; k0 += 32) {
        for (int i = tx; i < 32*128; i += 256) {
            int e = i & 31, m = i >> 5;
            As[e][m] = tokens[(m0+m)*512 + k0 + e];
        }
        for (int i = tx; i < 32*64; i += 256) {
            int e = i & 31, dch = i >> 5;
            Bs[e][dch] = Wt[dch*512 + k0 + e];
        }
        __syncthreads();
        #pragma unroll 4
        for (int kk = 0; kk < 32; kk++) {
            float4 a0 = *(const float4*)&As[kk][m_base];
            float4 a1 = *(const float4*)&As[kk][m_base+4];
            float4 bv = *(const float4*)&Bs[kk][n_base];
            float am[8] = {a0.x,a0.y,a0.z,a0.w,a1.x,a1.y,a1.z,a1.w};
            float bn[4] = {bv.x,bv.y,bv.z,bv.w};
            #pragma unroll
            for (int i2 = 0; i2 < 8; i2++)
                #pragma unroll
                for (int j = 0; j < 4; j++)
                    acc[i2][j] = fmaf(am[i2], bn[j], acc[i2][j]);
        }
        __syncthreads();
    }
    #pragma unroll
    for (int i2 = 0; i2 < 8; i2++) {
        float4 v = make_float4(acc[i2][0],acc[i2][1],acc[i2][2],acc[i2][3]);
        *(float4*)&g_proj[(m0+m_base+i2)*64 + n_base] = v;
    }
}

// ------- K2: scatter. field[b](64 x 4096) = proj^T * (gy ⊗ gx) ---------
__global__ void __launch_bounds__(256) k_scatter() {
    __shared__ float As[32][68];    // [k=l][c]
    __shared__ float Bs[32][132];   // [k][n=hw]
    int b  = blockIdx.y;
    int n0 = blockIdx.x * 128;      // hw tile (2 rows of 64)
    int h0 = n0 >> 6;
    int tx = threadIdx.x;
    int m_base = (tx >> 5) * 8;
    int n_base = (tx & 31) * 4;
    float acc[8][4] = {};
    for (int l0 = 0; l0 < L_; l0 += 32) {
        for (int i = tx; i < 32*64; i += 256) {
            int c = i & 63, k = i >> 6;
            As[k][c] = g_proj[((size_t)(b*L_) + l0 + k)*64 + c];
        }
        for (int i = tx; i < 32*128; i += 256) {
            int n = i & 127, k = i >> 7;
            int l = l0 + k;
            float gy = g_gyi[(b*L_+l)*64 + h0 + (n >> 6)];
            float gx = g_gxi[(b*L_+l)*64 + (n & 63)];
            Bs[k][n] = gy * gx;
        }
        __syncthreads();
        #pragma unroll 4
        for (int kk = 0; kk < 32; kk++) {
            float4 a0 = *(const float4*)&As[kk][m_base];
            float4 a1 = *(const float4*)&As[kk][m_base+4];
            float4 bv = *(const float4*)&Bs[kk][n_base];
            float am[8] = {a0.x,a0.y,a0.z,a0.w,a1.x,a1.y,a1.z,a1.w};
            float bn[4] = {bv.x,bv.y,bv.z,bv.w};
            #pragma unroll
            for (int i2 = 0; i2 < 8; i2++)
                #pragma unroll
                for (int j = 0; j < 4; j++)
                    acc[i2][j] = fmaf(am[i2], bn[j], acc[i2][j]);
        }
        __syncthreads();
    }
    #pragma unroll
    for (int i2 = 0; i2 < 8; i2++) {
        float4 v = make_float4(acc[i2][0],acc[i2][1],acc[i2][2],acc[i2][3]);
        *(float4*)&g_field[((size_t)(b*64) + m_base + i2)*HW + n0 + n_base] = v;
    }
}

// ---- K3: fused conv step.  out = in + conv2(relu(conv1(in))) ----
// Phase 1: h[128oc x 128px] = relu(conv1_3x3(in) + b1)  (K = 64ic*9 = 576)
// Phase 2: out[64c x 128px] = in + b2 + w2 * h          (K = 128)
// Dynamic smem layout (floats): hbuf[128*132] | As[36*132] | Bs[36*132]
#define SM_HB 0
#define SM_AS (128*132)
#define SM_BS (128*132 + 36*132)
#define SM_TOTAL_FLOATS (128*132 + 2*36*132)

__global__ void __launch_bounds__(256)
k_step(const float* __restrict__ w1, const float* __restrict__ b1,
       const float* __restrict__ w2, const float* __restrict__ b2,
       int parity) {
    extern __shared__ float sm[];
    float* hbuf = sm + SM_HB;
    float* As   = sm + SM_AS;
    float* Bs   = sm + SM_BS;

    const float* fin  = parity ? g_field2 : g_field;
    float*       fout = parity ? g_field  : g_field2;

    int b  = blockIdx.y;
    int y0 = blockIdx.x * 2;       // two output rows
    int p0 = y0 * 64;
    int tx = threadIdx.x;

    // ---------- Phase 1: conv1 (3x3, 64->128) ----------
    int m1 = (tx >> 4) * 8;        // oc, 16 groups of 8
    int n1 = (tx & 15) * 8;        // px, 16 groups of 8
    float acc[8][8] = {};
    for (int ic0 = 0; ic0 < 64; ic0 += 4) {
        // stage A: As[k][m] = w1[m*576 + ic0*9 + k], k in [0,36), m in [0,128)
        for (int i = tx; i < 36*128; i += 256) {
            int k = i % 36, m = i / 36;
            As[k*132 + m] = w1[m*576 + ic0*9 + k];
        }
        // stage B: halo reads of input field
        for (int i = tx; i < 36*128; i += 256) {
            int n = i & 127, k = i >> 7;
            int ici = k / 9, tap = k - ici*9;
            int ky = tap / 3, kx = tap - ky*3;
            int y = y0 + (n >> 6) + ky - 1;
            int x = (n & 63) + kx - 1;
            float v = 0.0f;
            if ((unsigned)y < 64u && (unsigned)x < 64u)
                v = fin[((size_t)(b*64) + ic0 + ici)*HW + y*64 + x];
            Bs[k*132 + n] = v;
        }
        __syncthreads();
        #pragma unroll 4
        for (int kk = 0; kk < 36; kk++) {
            float4 a0 = *(const float4*)&As[kk*132 + m1];
            float4 a1 = *(const float4*)&As[kk*132 + m1 + 4];
            float4 b0 = *(const float4*)&Bs[kk*132 + n1];
            float4 b1v = *(const float4*)&Bs[kk*132 + n1 + 4];
            float am[8] = {a0.x,a0.y,a0.z,a0.w,a1.x,a1.y,a1.z,a1.w};
            float bn[8] = {b0.x,b0.y,b0.z,b0.w,b1v.x,b1v.y,b1v.z,b1v.w};
            #pragma unroll
            for (int i2 = 0; i2 < 8; i2++)
                #pragma unroll
                for (int j = 0; j < 8; j++)
                    acc[i2][j] = fmaf(am[i2], bn[j], acc[i2][j]);
        }
        __syncthreads();
    }
    // bias + relu -> hbuf[oc][px]
    #pragma unroll
    for (int i2 = 0; i2 < 8; i2++) {
        int oc = m1 + i2;
        float bias = b1[oc];
        float4 v0 = make_float4(fmaxf(acc[i2][0]+bias,0.f), fmaxf(acc[i2][1]+bias,0.f),
                                fmaxf(acc[i2][2]+bias,0.f), fmaxf(acc[i2][3]+bias,0.f));
        float4 v1 = make_float4(fmaxf(acc[i2][4]+bias,0.f), fmaxf(acc[i2][5]+bias,0.f),
                                fmaxf(acc[i2][6]+bias,0.f), fmaxf(acc[i2][7]+bias,0.f));
        *(float4*)&hbuf[oc*132 + n1]     = v0;
        *(float4*)&hbuf[oc*132 + n1 + 4] = v1;
    }
    __syncthreads();

    // ---------- Phase 2: conv2 (1x1, 128->64) + bias + residual ----------
    int m2 = (tx >> 5) * 8;        // c, 8 groups of 8
    int n2 = (tx & 31) * 4;        // px, 32 groups of 4
    float acc2[8][4] = {};
    for (int k0 = 0; k0 < 128; k0 += 32) {
        // stage A: As[k][c] = w2[c*128 + k0 + k]   (reuse As region)
        for (int i = tx; i < 32*64; i += 256) {
            int k = i & 31, c = i >> 5;
            As[k*68 + c] = w2[c*128 + k0 + k];
        }
        __syncthreads();
        #pragma unroll 8
        for (int kk = 0; kk < 32; kk++) {
            float4 a0 = *(const float4*)&As[kk*68 + m2];
            float4 a1 = *(const float4*)&As[kk*68 + m2 + 4];
            float4 bv = *(const float4*)&hbuf[(k0+kk)*132 + n2];
            float am[8] = {a0.x,a0.y,a0.z,a0.w,a1.x,a1.y,a1.z,a1.w};
            float bn[4] = {bv.x,bv.y,bv.z,bv.w};
            #pragma unroll
            for (int i2 = 0; i2 < 8; i2++)
                #pragma unroll
                for (int j = 0; j < 4; j++)
                    acc2[i2][j] = fmaf(am[i2], bn[j], acc2[i2][j]);
        }
        __syncthreads();
    }
    #pragma unroll
    for (int i2 = 0; i2 < 8; i2++) {
        int c = m2 + i2;
        float bias = b2[c];
        size_t off = ((size_t)(b*64) + c)*HW + p0 + n2;
        float4 r = *(const float4*)&fin[off];
        float4 v = make_float4(acc2[i2][0]+bias+r.x, acc2[i2][1]+bias+r.y,
                               acc2[i2][2]+bias+r.z, acc2[i2][3]+bias+r.w);
        *(float4*)&fout[off] = v;
    }
}

// ---- K5: gather. sampled[b](L x 64) = (gyo ⊗ gxo) * field^T ----
// reads g_field2 (final buffer after odd number of steps)
__global__ void __launch_bounds__(256) k_gather() {
    __shared__ float As[64][68];    // [k=w][l]
    __shared__ float Bs[64][68];    // [k=w][c]
    int b  = blockIdx.y;
    int l0 = blockIdx.x * 64;
    int tx = threadIdx.x;
    int m_base = (tx >> 4) * 4;     // l
    int n_base = (tx & 15) * 4;     // c
    float acc[4][4] = {};
    for (int h = 0; h < 64; h++) {
        for (int i = tx; i < 64*64; i += 256) {
            int w = i & 63, l = i >> 6;
            float gy = g_gyo[(b*L_ + l0 + l)*64 + h];
            float gx = g_gxo[(b*L_ + l0 + l)*64 + w];
            As[w][l] = gy * gx;
        }
        for (int i = tx; i < 64*64; i += 256) {
            int w = i & 63, c = i >> 6;
            Bs[w][c] = g_field2[((size_t)(b*64) + c)*HW + h*64 + w];
        }
        __syncthreads();
        #pragma unroll 4
        for (int kk = 0; kk < 64; kk++) {
            float4 a = *(const float4*)&As[kk][m_base];
            float4 bv = *(const float4*)&Bs[kk][n_base];
            float am[4] = {a.x,a.y,a.z,a.w};
            float bn[4] = {bv.x,bv.y,bv.z,bv.w};
            #pragma unroll
            for (int i2 = 0; i2 < 4; i2++)
                #pragma unroll
                for (int j = 0; j < 4; j++)
                    acc[i2][j] = fmaf(am[i2], bn[j], acc[i2][j]);
        }
        __syncthreads();
    }
    #pragma unroll
    for (int i2 = 0; i2 < 4; i2++) {
        float4 v = make_float4(acc[i2][0],acc[i2][1],acc[i2][2],acc[i2][3]);
        *(float4*)&g_sampled[((size_t)(b*L_) + l0 + m_base + i2)*64 + n_base] = v;
    }
}

// ---- K6: tokens_out = sampled @ W_from_field^T  (16384x512, K=64) ----
__global__ void __launch_bounds__(256)
k_out(const float* __restrict__ Wf, float* __restrict__ out) {
    __shared__ float As[64][68];    // [c][m=l]
    __shared__ float Bs[64][68];    // [c][e]
    int m0 = blockIdx.x * 64;
    int e0 = blockIdx.y * 64;
    int tx = threadIdx.x;
    int m_base = (tx >> 4) * 4;
    int n_base = (tx & 15) * 4;
    float acc[4][4] = {};
    for (int i = tx; i < 64*64; i += 256) {
        int c = i & 63, m = i >> 6;
        As[c][m] = g_sampled[(size_t)(m0+m)*64 + c];
    }
    for (int i = tx; i < 64*64; i += 256) {
        int c = i & 63, e = i >> 6;
        Bs[c][e] = Wf[(e0+e)*64 + c];
    }
    __syncthreads();
    #pragma unroll 4
    for (int kk = 0; kk < 64; kk++) {
        float4 a = *(const float4*)&As[kk][m_base];
        float4 bv = *(const float4*)&Bs[kk][n_base];
        float am[4] = {a.x,a.y,a.z,a.w};
        float bn[4] = {bv.x,bv.y,bv.z,bv.w};
        #pragma unroll
        for (int i2 = 0; i2 < 4; i2++)
            #pragma unroll
            for (int j = 0; j < 4; j++)
                acc[i2][j] = fmaf(am[i2], bn[j], acc[i2][j]);
    }
    #pragma unroll
    for (int i2 = 0; i2 < 4; i2++) {
        float4 v = make_float4(acc[i2][0],acc[i2][1],acc[i2][2],acc[i2][3]);
        *(float4*)&out[(size_t)(m0+m_base+i2)*512 + e0 + n_base] = v;
    }
}

// ------------------------------ launch -----------------------------------
extern "C" void kernel_launch(void* const* d_in, const int* in_sizes, int n_in,
                              void* d_out, int out_size) {
    const float* tokens     = (const float*)d_in[0];
    const float* positions  = (const float*)d_in[1];
    const float* W_to_field = (const float*)d_in[2];
    const float* W_from_field = (const float*)d_in[3];
    const float* conv1_w    = (const float*)d_in[4];
    const float* conv1_b    = (const float*)d_in[5];
    const float* conv2_w    = (const float*)d_in[6];
    const float* conv2_b    = (const float*)d_in[7];
    const float* log_sigma  = (const float*)d_in[8];
    float* out = (float*)d_out;

    const int smem_bytes = SM_TOTAL_FLOATS * 4;   // 105,600 B
    cudaFuncSetAttribute(k_step, cudaFuncAttributeMaxDynamicSharedMemorySize,
                         smem_bytes);

    k_gauss<<<B_*L_, 64>>>(positions, log_sigma);
    k_proj<<<(B_*L_)/128, 256>>>(tokens, W_to_field);
    k_scatter<<<dim3(32, B_), 256>>>();
    for (int s = 0; s < STEPS_; s++) {
        k_step<<<dim3(32, B_), 256, smem_bytes>>>(conv1_w, conv1_b,
                                                  conv2_w, conv2_b, s & 1);
    }
    k_gather<<<dim3(32, B_), 256>>>();
    k_out<<<dim3((B_*L_)/64, 8), 256>>>(W_from_field, out);
}

// round 4
// speedup vs baseline: 1.2062x; 1.0739x over previous
#include <cuda_runtime.h>
#include <math.h>

#define B_ 8
#define L_ 2048
#define E_ 512
#define D_ 64
#define HH 64
#define WW 64
#define HW 4096
#define STEPS_ 5

typedef unsigned long long u64;

// packed fp32x2 helpers (sm_103a FFMA2 — only reachable via PTX)
__device__ __forceinline__ u64 dup2(float x) {
    u64 r; asm("mov.b64 %0, {%1, %1};" : "=l"(r) : "f"(x)); return r;
}
__device__ __forceinline__ void fma2(u64& d, u64 a, u64 b) {
    asm("fma.rn.f32x2 %0, %1, %2, %0;" : "+l"(d) : "l"(a), "l"(b));
}
__device__ __forceinline__ float2 f2u(u64 v) {
    float2 f; asm("mov.b64 {%0, %1}, %2;" : "=f"(f.x), "=f"(f.y) : "l"(v)); return f;
}

// ---------------- scratch (device globals; no allocation) ----------------
__device__ float g_gyi[B_*L_*HH];
__device__ float g_gxi[B_*L_*WW];
__device__ float g_gyo[B_*L_*HH];
__device__ float g_gxo[B_*L_*WW];
__device__ float g_proj[B_*L_*D_];
__device__ float g_field[B_*D_*HW];     // buffer A
__device__ float g_field2[B_*D_*HW];    // buffer B
__device__ float g_sampled[B_*L_*D_];

// ---------------- K0: separable gaussians + normalizers ----------------
__global__ void k_gauss(const float* __restrict__ pos,
                        const float* __restrict__ log_sigma) {
    int bl = blockIdx.x;
    int t  = threadIdx.x;   // 0..63
    float ls = *log_sigma;
    float si = log1pf(expf(ls)) + 1e-6f;
    float so = 2.0f * si;
    float i2si = 1.0f / (2.0f * si * si);
    float i2so = 1.0f / (2.0f * so * so);
    float py = pos[bl*2+0];
    float px = pos[bl*2+1];
    float d  = (float)t;
    float dy2 = (d - py) * (d - py);
    float dx2 = (d - px) * (d - px);
    float gy  = expf(-dy2 * i2si);
    float gx  = expf(-dx2 * i2si);
    float gyo = expf(-dy2 * i2so);
    float gxo = expf(-dx2 * i2so);
    __shared__ float red[4][64];
    __shared__ float sums[4];
    red[0][t]=gy; red[1][t]=gx; red[2][t]=gyo; red[3][t]=gxo;
    __syncthreads();
    if (t < 4) {
        float s = 0.0f;
        #pragma unroll
        for (int i = 0; i < 64; i++) s += red[t][i];
        sums[t] = s;
    }
    __syncthreads();
    float inv_ni = 1.0f / (sums[0]*sums[1] + 1e-6f);
    float inv_no = 1.0f / (sums[2]*sums[3] + 1e-6f);
    int base = bl*64 + t;
    g_gyi[base] = gy  * inv_ni;
    g_gxi[base] = gx;
    g_gyo[base] = gyo * inv_no;
    g_gxo[base] = gxo;
}

// ---------------- K1: proj = tokens @ W_to_field^T  (16384x64, K=512) ----
__global__ void __launch_bounds__(256)
k_proj(const float* __restrict__ tokens, const float* __restrict__ Wt) {
    __shared__ float As[32][132];   // [e][m]
    __shared__ float Bs[32][68];    // [e][d]
    int m0 = blockIdx.x * 128;
    int tx = threadIdx.x;
    int m_base = (tx >> 4) * 8;
    int n_base = (tx & 15) * 4;
    u64 acc[4][4] = {};             // [m_pair][n]
    for (int k0 = 0; k0 < 512; k0 += 32) {
        for (int i = tx; i < 32*128; i += 256) {
            int e = i & 31, m = i >> 5;
            As[e][m] = tokens[(m0+m)*512 + k0 + e];
        }
        for (int i = tx; i < 32*64; i += 256) {
            int e = i & 31, dch = i >> 5;
            Bs[e][dch] = Wt[dch*512 + k0 + e];
        }
        __syncthreads();
        #pragma unroll 4
        for (int kk = 0; kk < 32; kk++) {
            ulonglong2 a01 = *(const ulonglong2*)&As[kk][m_base];
            ulonglong2 a23 = *(const ulonglong2*)&As[kk][m_base+4];
            u64 ap[4] = {a01.x, a01.y, a23.x, a23.y};
            float4 bv = *(const float4*)&Bs[kk][n_base];
            u64 bd[4] = {dup2(bv.x), dup2(bv.y), dup2(bv.z), dup2(bv.w)};
            #pragma unroll
            for (int p = 0; p < 4; p++)
                #pragma unroll
                for (int j = 0; j < 4; j++)
                    fma2(acc[p][j], ap[p], bd[j]);
        }
        __syncthreads();
    }
    #pragma unroll
    for (int p = 0; p < 4; p++) {
        float2 q0 = f2u(acc[p][0]), q1 = f2u(acc[p][1]);
        float2 q2 = f2u(acc[p][2]), q3 = f2u(acc[p][3]);
        int m = m0 + m_base + 2*p;
        *(float4*)&g_proj[(size_t)m*64 + n_base]     = make_float4(q0.x,q1.x,q2.x,q3.x);
        *(float4*)&g_proj[(size_t)(m+1)*64 + n_base] = make_float4(q0.y,q1.y,q2.y,q3.y);
    }
}

// ------- K2: scatter. field[b](64 x 4096) = proj^T * (gy ⊗ gx) ---------
__global__ void __launch_bounds__(256) k_scatter() {
    __shared__ float As[32][68];    // [k=l][c]
    __shared__ float Bs[32][132];   // [k][n=hw]
    int b  = blockIdx.y;
    int n0 = blockIdx.x * 128;
    int h0 = n0 >> 6;
    int tx = threadIdx.x;
    int m_base = (tx >> 5) * 8;
    int n_base = (tx & 31) * 4;
    u64 acc[4][4] = {};             // [c_pair][n]
    for (int l0 = 0; l0 < L_; l0 += 32) {
        for (int i = tx; i < 32*64; i += 256) {
            int c = i & 63, k = i >> 6;
            As[k][c] = g_proj[((size_t)(b*L_) + l0 + k)*64 + c];
        }
        for (int i = tx; i < 32*128; i += 256) {
            int n = i & 127, k = i >> 7;
            int l = l0 + k;
            float gy = g_gyi[(b*L_+l)*64 + h0 + (n >> 6)];
            float gx = g_gxi[(b*L_+l)*64 + (n & 63)];
            Bs[k][n] = gy * gx;
        }
        __syncthreads();
        #pragma unroll 4
        for (int kk = 0; kk < 32; kk++) {
            ulonglong2 a01 = *(const ulonglong2*)&As[kk][m_base];
            ulonglong2 a23 = *(const ulonglong2*)&As[kk][m_base+4];
            u64 ap[4] = {a01.x, a01.y, a23.x, a23.y};
            float4 bv = *(const float4*)&Bs[kk][n_base];
            u64 bd[4] = {dup2(bv.x), dup2(bv.y), dup2(bv.z), dup2(bv.w)};
            #pragma unroll
            for (int p = 0; p < 4; p++)
                #pragma unroll
                for (int j = 0; j < 4; j++)
                    fma2(acc[p][j], ap[p], bd[j]);
        }
        __syncthreads();
    }
    #pragma unroll
    for (int p = 0; p < 4; p++) {
        float2 q0 = f2u(acc[p][0]), q1 = f2u(acc[p][1]);
        float2 q2 = f2u(acc[p][2]), q3 = f2u(acc[p][3]);
        int c = m_base + 2*p;
        *(float4*)&g_field[((size_t)(b*64) + c)*HW + n0 + n_base]
            = make_float4(q0.x,q1.x,q2.x,q3.x);
        *(float4*)&g_field[((size_t)(b*64) + c+1)*HW + n0 + n_base]
            = make_float4(q0.y,q1.y,q2.y,q3.y);
    }
}

// ---- K3: fused conv step.  out = in + conv2(relu(conv1(in))) ----
#define SM_HB 0
#define SM_AS (128*132)
#define SM_BS (128*132 + 36*132)
#define SM_TOTAL_FLOATS (128*132 + 2*36*132)

__global__ void __launch_bounds__(256, 2)
k_step(const float* __restrict__ w1, const float* __restrict__ bias1,
       const float* __restrict__ w2, const float* __restrict__ bias2,
       int parity) {
    extern __shared__ float sm[];
    float* hbuf = sm + SM_HB;
    float* As   = sm + SM_AS;
    float* Bs   = sm + SM_BS;

    const float* fin  = parity ? g_field2 : g_field;
    float*       fout = parity ? g_field  : g_field2;

    int b  = blockIdx.y;
    int y0 = blockIdx.x * 2;
    int p0 = y0 * 64;
    int tx = threadIdx.x;

    // ---------- Phase 1: conv1 (3x3, 64->128) ----------
    int m1 = (tx >> 4) * 8;        // oc
    int n1 = (tx & 15) * 8;        // px
    u64 acc[8][4] = {};            // [oc][px_pair]
    for (int ic0 = 0; ic0 < 64; ic0 += 4) {
        for (int i = tx; i < 36*128; i += 256) {
            int k = i % 36, m = i / 36;
            As[k*132 + m] = w1[m*576 + ic0*9 + k];
        }
        for (int i = tx; i < 36*128; i += 256) {
            int n = i & 127, k = i >> 7;
            int ici = k / 9, tap = k - ici*9;
            int ky = tap / 3, kx = tap - ky*3;
            int y = y0 + (n >> 6) + ky - 1;
            int x = (n & 63) + kx - 1;
            float v = 0.0f;
            if ((unsigned)y < 64u && (unsigned)x < 64u)
                v = fin[((size_t)(b*64) + ic0 + ici)*HW + y*64 + x];
            Bs[k*132 + n] = v;
        }
        __syncthreads();
        #pragma unroll 4
        for (int kk = 0; kk < 36; kk++) {
            float4 a0 = *(const float4*)&As[kk*132 + m1];
            float4 a1 = *(const float4*)&As[kk*132 + m1 + 4];
            u64 am[8] = {dup2(a0.x),dup2(a0.y),dup2(a0.z),dup2(a0.w),
                         dup2(a1.x),dup2(a1.y),dup2(a1.z),dup2(a1.w)};
            ulonglong2 b01 = *(const ulonglong2*)&Bs[kk*132 + n1];
            ulonglong2 b23 = *(const ulonglong2*)&Bs[kk*132 + n1 + 4];
            u64 bn[4] = {b01.x, b01.y, b23.x, b23.y};
            #pragma unroll
            for (int i2 = 0; i2 < 8; i2++)
                #pragma unroll
                for (int j = 0; j < 4; j++)
                    fma2(acc[i2][j], am[i2], bn[j]);
        }
        __syncthreads();
    }
    // bias + relu -> hbuf[oc][px]
    #pragma unroll
    for (int i2 = 0; i2 < 8; i2++) {
        int oc = m1 + i2;
        float bias = bias1[oc];
        float2 q0 = f2u(acc[i2][0]), q1 = f2u(acc[i2][1]);
        float2 q2 = f2u(acc[i2][2]), q3 = f2u(acc[i2][3]);
        float4 v0 = make_float4(fmaxf(q0.x+bias,0.f), fmaxf(q0.y+bias,0.f),
                                fmaxf(q1.x+bias,0.f), fmaxf(q1.y+bias,0.f));
        float4 v1 = make_float4(fmaxf(q2.x+bias,0.f), fmaxf(q2.y+bias,0.f),
                                fmaxf(q3.x+bias,0.f), fmaxf(q3.y+bias,0.f));
        *(float4*)&hbuf[oc*132 + n1]     = v0;
        *(float4*)&hbuf[oc*132 + n1 + 4] = v1;
    }
    __syncthreads();

    // ---------- Phase 2: conv2 (1x1, 128->64) + bias + residual ----------
    int m2 = (tx >> 5) * 8;        // c
    int n2 = (tx & 31) * 4;        // px
    u64 acc2[4][4] = {};           // [c_pair][px]
    for (int k0 = 0; k0 < 128; k0 += 32) {
        for (int i = tx; i < 32*64; i += 256) {
            int k = i & 31, c = i >> 5;
            As[k*68 + c] = w2[c*128 + k0 + k];
        }
        __syncthreads();
        #pragma unroll 8
        for (int kk = 0; kk < 32; kk++) {
            ulonglong2 a01 = *(const ulonglong2*)&As[kk*68 + m2];
            ulonglong2 a23 = *(const ulonglong2*)&As[kk*68 + m2 + 4];
            u64 ap[4] = {a01.x, a01.y, a23.x, a23.y};
            float4 bv = *(const float4*)&hbuf[(k0+kk)*132 + n2];
            u64 bd[4] = {dup2(bv.x), dup2(bv.y), dup2(bv.z), dup2(bv.w)};
            #pragma unroll
            for (int p = 0; p < 4; p++)
                #pragma unroll
                for (int j = 0; j < 4; j++)
                    fma2(acc2[p][j], ap[p], bd[j]);
        }
        __syncthreads();
    }
    #pragma unroll
    for (int p = 0; p < 4; p++) {
        float2 q0 = f2u(acc2[p][0]), q1 = f2u(acc2[p][1]);
        float2 q2 = f2u(acc2[p][2]), q3 = f2u(acc2[p][3]);
        int c0 = m2 + 2*p;
        float bA = bias2[c0], bB = bias2[c0+1];
        size_t offA = ((size_t)(b*64) + c0)*HW + p0 + n2;
        size_t offB = offA + HW;
        float4 rA = *(const float4*)&fin[offA];
        float4 rB = *(const float4*)&fin[offB];
        *(float4*)&fout[offA] = make_float4(q0.x+bA+rA.x, q1.x+bA+rA.y,
                                            q2.x+bA+rA.z, q3.x+bA+rA.w);
        *(float4*)&fout[offB] = make_float4(q0.y+bB+rB.x, q1.y+bB+rB.y,
                                            q2.y+bB+rB.z, q3.y+bB+rB.w);
    }
}

// ---- K5: gather. sampled[b](L x 64) = (gyo ⊗ gxo) * field^T ----
__global__ void __launch_bounds__(256) k_gather() {
    __shared__ float As[64][68];    // [k=w][l]
    __shared__ float Bs[64][68];    // [k=w][c]
    int b  = blockIdx.y;
    int l0 = blockIdx.x * 64;
    int tx = threadIdx.x;
    int m_base = (tx >> 4) * 4;     // l
    int n_base = (tx & 15) * 4;     // c
    u64 acc[4][2] = {};             // [l][c_pair]
    for (int h = 0; h < 64; h++) {
        for (int i = tx; i < 64*64; i += 256) {
            int w = i & 63, l = i >> 6;
            float gy = g_gyo[(b*L_ + l0 + l)*64 + h];
            float gx = g_gxo[(b*L_ + l0 + l)*64 + w];
            As[w][l] = gy * gx;
        }
        for (int i = tx; i < 64*64; i += 256) {
            int w = i & 63, c = i >> 6;
            Bs[w][c] = g_field2[((size_t)(b*64) + c)*HW + h*64 + w];
        }
        __syncthreads();
        #pragma unroll 4
        for (int kk = 0; kk < 64; kk++) {
            float4 a = *(const float4*)&As[kk][m_base];
            u64 ad[4] = {dup2(a.x), dup2(a.y), dup2(a.z), dup2(a.w)};
            ulonglong2 bp = *(const ulonglong2*)&Bs[kk][n_base];
            u64 bn[2] = {bp.x, bp.y};
            #pragma unroll
            for (int i2 = 0; i2 < 4; i2++)
                #pragma unroll
                for (int j = 0; j < 2; j++)
                    fma2(acc[i2][j], ad[i2], bn[j]);
        }
        __syncthreads();
    }
    #pragma unroll
    for (int i2 = 0; i2 < 4; i2++) {
        float2 q0 = f2u(acc[i2][0]), q1 = f2u(acc[i2][1]);
        *(float4*)&g_sampled[((size_t)(b*L_) + l0 + m_base + i2)*64 + n_base]
            = make_float4(q0.x, q0.y, q1.x, q1.y);
    }
}

// ---- K6: tokens_out = sampled @ W_from_field^T  (16384x512, K=64) ----
__global__ void __launch_bounds__(256)
k_out(const float* __restrict__ Wf, float* __restrict__ out) {
    __shared__ float As[64][68];    // [c][m=l]
    __shared__ float Bs[64][68];    // [c][e]
    int m0 = blockIdx.x * 64;
    int e0 = blockIdx.y * 64;
    int tx = threadIdx.x;
    int m_base = (tx >> 4) * 4;
    int n_base = (tx & 15) * 4;
    u64 acc[4][2] = {};
    for (int i = tx; i < 64*64; i += 256) {
        int c = i & 63, m = i >> 6;
        As[c][m] = g_sampled[(size_t)(m0+m)*64 + c];
    }
    for (int i = tx; i < 64*64; i += 256) {
        int c = i & 63, e = i >> 6;
        Bs[c][e] = Wf[(e0+e)*64 + c];
    }
    __syncthreads();
    #pragma unroll 4
    for (int kk = 0; kk < 64; kk++) {
        float4 a = *(const float4*)&As[kk][m_base];
        u64 ad[4] = {dup2(a.x), dup2(a.y), dup2(a.z), dup2(a.w)};
        ulonglong2 bp = *(const ulonglong2*)&Bs[kk][n_base];
        u64 bn[2] = {bp.x, bp.y};
        #pragma unroll
        for (int i2 = 0; i2 < 4; i2++)
            #pragma unroll
            for (int j = 0; j < 2; j++)
                fma2(acc[i2][j], ad[i2], bn[j]);
    }
    #pragma unroll
    for (int i2 = 0; i2 < 4; i2++) {
        float2 q0 = f2u(acc[i2][0]), q1 = f2u(acc[i2][1]);
        *(float4*)&out[(size_t)(m0+m_base+i2)*512 + e0 + n_base]
            = make_float4(q0.x, q0.y, q1.x, q1.y);
    }
}

// ------------------------------ launch -----------------------------------
extern "C" void kernel_launch(void* const* d_in, const int* in_sizes, int n_in,
                              void* d_out, int out_size) {
    const float* tokens     = (const float*)d_in[0];
    const float* positions  = (const float*)d_in[1];
    const float* W_to_field = (const float*)d_in[2];
    const float* W_from_field = (const float*)d_in[3];
    const float* conv1_w    = (const float*)d_in[4];
    const float* conv1_b    = (const float*)d_in[5];
    const float* conv2_w    = (const float*)d_in[6];
    const float* conv2_b    = (const float*)d_in[7];
    const float* log_sigma  = (const float*)d_in[8];
    float* out = (float*)d_out;

    const int smem_bytes = SM_TOTAL_FLOATS * 4;   // 105,600 B
    cudaFuncSetAttribute(k_step, cudaFuncAttributeMaxDynamicSharedMemorySize,
                         smem_bytes);

    k_gauss<<<B_*L_, 64>>>(positions, log_sigma);
    k_proj<<<(B_*L_)/128, 256>>>(tokens, W_to_field);
    k_scatter<<<dim3(32, B_), 256>>>();
    for (int s = 0; s < STEPS_; s++) {
        k_step<<<dim3(32, B_), 256, smem_bytes>>>(conv1_w, conv1_b,
                                                  conv2_w, conv2_b, s & 1);
    }
    k_gather<<<dim3(32, B_), 256>>>();
    k_out<<<dim3((B_*L_)/64, 8), 256>>>(W_from_field, out);
}